// round 2
// baseline (speedup 1.0000x reference)
#include <cuda_runtime.h>
#include <math.h>

#define NN 10000
#define EE 160000
#define CC 32
#define NB 128
#define HH 64
#define FD 512   // C * (1+3+5+7)

// ---------------- scratch (device globals; no allocation) ----------------
__device__ float g_h[(size_t)EE*HH];     // 41 MB  : hidden per edge
__device__ float g_sh[(size_t)EE*16];    // 10 MB  : spherical harmonics per edge
__device__ float g_w[(size_t)EE*FD];     // 328 MB : [w_all(384) | ew(128)] per edge
__device__ float g_fa[(size_t)NN*FD];    // 20 MB  : node features buf A
__device__ float g_fb[(size_t)NN*FD];    // 20 MB  : node features buf B
__device__ int   g_cnt[NN];
__device__ int   g_off[NN+1];
__device__ int   g_eid[EE];

// ---------------- helpers ----------------
__device__ __forceinline__ float to_tf32(float x) {
    float r;
    asm("cvt.rna.tf32.f32 %0, %1;" : "=f"(r) : "f"(x));
    return r;
}

__device__ __forceinline__ void mma_tf32(float* d, const unsigned* a, const unsigned* b) {
    asm volatile("mma.sync.aligned.m16n8k8.row.col.f32.tf32.tf32.f32 "
        "{%0,%1,%2,%3}, {%4,%5,%6,%7}, {%8,%9}, {%0,%1,%2,%3};"
        : "+f"(d[0]), "+f"(d[1]), "+f"(d[2]), "+f"(d[3])
        : "r"(a[0]), "r"(a[1]), "r"(a[2]), "r"(a[3]), "r"(b[0]), "r"(b[1]));
}

// ---------------- CSR build ----------------
__global__ void k_zero_cnt() {
    int i = blockIdx.x*blockDim.x + threadIdx.x;
    if (i < NN) g_cnt[i] = 0;
}

__global__ void k_hist(const int* __restrict__ ei) {
    int e = blockIdx.x*blockDim.x + threadIdx.x;
    if (e < EE) atomicAdd(&g_cnt[ei[EE + e]], 1);
}

__global__ void k_scan() {
    __shared__ int sdat[1024];
    __shared__ int carry;
    int tid = threadIdx.x;
    if (tid == 0) { carry = 0; g_off[0] = 0; }
    __syncthreads();
    for (int base = 0; base < NN; base += 1024) {
        int i = base + tid;
        int v = (i < NN) ? g_cnt[i] : 0;
        sdat[tid] = v;
        __syncthreads();
        for (int o = 1; o < 1024; o <<= 1) {
            int t = (tid >= o) ? sdat[tid - o] : 0;
            __syncthreads();
            sdat[tid] += t;
            __syncthreads();
        }
        int incl = sdat[tid] + carry;
        if (i < NN) g_off[i+1] = incl;
        __syncthreads();
        if (tid == 1023) carry = incl;
        __syncthreads();
    }
}

__global__ void k_fill(const int* __restrict__ ei) {
    int e = blockIdx.x*blockDim.x + threadIdx.x;
    if (e < EE) {
        int d = ei[EE + e];
        int p = atomicAdd(&g_cnt[d], 1);
        g_eid[g_off[d] + p] = e;
    }
}

// ---------------- edge geometry + radial basis + first MLP layer ----------------
__global__ void k_geom(const float* __restrict__ pos, const float* __restrict__ rw1,
                       const float* __restrict__ rb1, const int* __restrict__ ei) {
    __shared__ float s_rw1[NB*HH];      // 32 KB
    __shared__ float s_rb[8][NB];       // 4 KB
    int tid = threadIdx.x;
    for (int i = tid; i < NB*HH; i += 256) s_rw1[i] = rw1[i];
    __syncthreads();

    int wid = tid >> 5, lane = tid & 31;
    int ebase = blockIdx.x*128 + wid*16;

    for (int j = 0; j < 16; j++) {
        int e = ebase + j;
        int sn = ei[e], dn = ei[EE + e];
        float vx = pos[dn*3+0] - pos[sn*3+0];
        float vy = pos[dn*3+1] - pos[sn*3+1];
        float vz = pos[dn*3+2] - pos[sn*3+2];
        float r2 = vx*vx + vy*vy + vz*vz + 1e-12f;
        float r  = sqrtf(r2);
        float inv_r = 1.0f / r;
        float x = vx*inv_r, y = vy*inv_r, z = vz*inv_r;

        if (lane < 16) {
            const float s3  = 1.7320508075688772f;
            const float s15 = 3.872983346207417f;
            const float s5h = 1.118033988749895f;
            const float s15h= 1.9364916731037085f;
            const float c1  = 2.091650066335189f;
            const float c2  = 10.246950765959598f;
            const float c3  = 1.6201851746019651f;
            const float c4  = 1.3228756555322954f;
            const float c5  = 5.123475382979799f;
            float sv;
            switch (lane) {
                case 0:  sv = 1.0f; break;
                case 1:  sv = s3*x; break;
                case 2:  sv = s3*y; break;
                case 3:  sv = s3*z; break;
                case 4:  sv = s15*x*y; break;
                case 5:  sv = s15*y*z; break;
                case 6:  sv = s5h*(3.0f*z*z - 1.0f); break;
                case 7:  sv = s15*x*z; break;
                case 8:  sv = s15h*(x*x - y*y); break;
                case 9:  sv = c1*y*(3.0f*x*x - y*y); break;
                case 10: sv = c2*x*y*z; break;
                case 11: sv = c3*y*(5.0f*z*z - 1.0f); break;
                case 12: sv = c4*(5.0f*z*z*z - 3.0f*z); break;
                case 13: sv = c3*x*(5.0f*z*z - 1.0f); break;
                case 14: sv = c5*z*(x*x - y*y); break;
                default: sv = c1*x*(x*x - 3.0f*y*y); break;
            }
            g_sh[(size_t)e*16 + lane] = sv;
        }

        float u = fminf(r * 0.2f, 1.0f);                 // r / RC, RC = 5
        float env = 0.5f * (cospif(u) + 1.0f);
        float scale = env * 0.6324555320336759f * inv_r; // sqrt(2/RC)

        #pragma unroll
        for (int q = 0; q < 4; q++) {
            int i = lane + q*32;
            s_rb[wid][i] = scale * sinpif((float)(i+1) * u);
        }
        __syncwarp();

        float a0 = 0.f, a1 = 0.f;
        #pragma unroll 8
        for (int i = 0; i < NB; i++) {
            float rbv = s_rb[wid][i];
            float2 w = *(const float2*)&s_rw1[i*HH + 2*lane];
            a0 += rbv * w.x;
            a1 += rbv * w.y;
        }
        a0 += rb1[2*lane];
        a1 += rb1[2*lane+1];
        a0 = a0 / (1.0f + expf(-a0));   // silu
        a1 = a1 / (1.0f + expf(-a1));
        ((float2*)&g_h[(size_t)e*HH])[lane] = make_float2(a0, a1);
        __syncwarp();
    }
}

// ---------------- GEMM (tf32 tensor cores) ----------------
// g_w = g_h (E x 64) @ [rw2 | edge_w] (64 x 512) + bias
// Block tile 128x128, K staged 2x32. 256 threads = 8 warps in 2(M) x 4(N).
// Each warp: 64x32 via m16n8k8 (4 m-tiles x 4 n-tiles).
#define AS_STR 36
#define BS_STR 136
__global__ void k_gemm(const float* __restrict__ rw2, const float* __restrict__ edge_w,
                       const float* __restrict__ rb2, const float* __restrict__ edge_b) {
    __shared__ float As[128*AS_STR];   // 18 KB
    __shared__ float Bs[32*BS_STR];    // 17 KB
    int tid = threadIdx.x;
    int bx = blockIdx.x, by = blockIdx.y;
    int lane = tid & 31, wid = tid >> 5;
    int wm = wid & 1, wn = wid >> 1;
    int lq = lane >> 2, lr = lane & 3;

    float acc[4][4][4];
    #pragma unroll
    for (int mt = 0; mt < 4; mt++)
        #pragma unroll
        for (int nt = 0; nt < 4; nt++)
            #pragma unroll
            for (int v = 0; v < 4; v++) acc[mt][nt][v] = 0.f;

    // per-thread bias (2 output cols per n-tile)
    float2 bias[4];
    #pragma unroll
    for (int nt = 0; nt < 4; nt++) {
        int jg = by*128 + wn*32 + nt*8 + lr*2;
        bias[nt].x = (jg < 384) ? rb2[jg]   : edge_b[jg - 384];
        bias[nt].y = (jg+1 < 384) ? rb2[jg+1] : edge_b[jg+1 - 384];
    }

    #pragma unroll
    for (int kk = 0; kk < 2; kk++) {
        // stage A: 128 rows x 32 k  (tf32-rounded)
        #pragma unroll
        for (int p = 0; p < 4; p++) {
            int li = tid + p*256;            // over 128 x 8 float4
            int row = li >> 3, c4 = li & 7;
            float4 v = *(const float4*)&g_h[(size_t)(bx*128 + row)*64 + kk*32 + c4*4];
            float4 t = make_float4(to_tf32(v.x), to_tf32(v.y), to_tf32(v.z), to_tf32(v.w));
            *(float4*)&As[row*AS_STR + c4*4] = t;
        }
        // stage B: 32 k x 128 n
        #pragma unroll
        for (int p = 0; p < 4; p++) {
            int li = tid + p*256;            // over 32 x 32 float4
            int krow = li >> 5, c4 = li & 31;
            int k = kk*32 + krow;
            int jg = by*128 + c4*4;
            float4 v = (jg < 384) ? *(const float4*)&rw2[k*384 + jg]
                                  : *(const float4*)&edge_w[k*128 + (jg - 384)];
            float4 t = make_float4(to_tf32(v.x), to_tf32(v.y), to_tf32(v.z), to_tf32(v.w));
            *(float4*)&Bs[krow*BS_STR + c4*4] = t;
        }
        __syncthreads();

        #pragma unroll
        for (int k0 = 0; k0 < 32; k0 += 8) {
            unsigned a[4][4], b[4][2];
            #pragma unroll
            for (int mt = 0; mt < 4; mt++) {
                int r = wm*64 + mt*16 + lq;
                a[mt][0] = __float_as_uint(As[r*AS_STR + k0 + lr]);
                a[mt][1] = __float_as_uint(As[(r+8)*AS_STR + k0 + lr]);
                a[mt][2] = __float_as_uint(As[r*AS_STR + k0 + lr + 4]);
                a[mt][3] = __float_as_uint(As[(r+8)*AS_STR + k0 + lr + 4]);
            }
            #pragma unroll
            for (int nt = 0; nt < 4; nt++) {
                int cl = wn*32 + nt*8 + lq;
                b[nt][0] = __float_as_uint(Bs[(k0 + lr)*BS_STR + cl]);
                b[nt][1] = __float_as_uint(Bs[(k0 + 4 + lr)*BS_STR + cl]);
            }
            #pragma unroll
            for (int mt = 0; mt < 4; mt++)
                #pragma unroll
                for (int nt = 0; nt < 4; nt++)
                    mma_tf32(acc[mt][nt], a[mt], b[nt]);
        }
        __syncthreads();
    }

    // write C (+bias). Each lane-quad writes one 32B sector.
    #pragma unroll
    for (int mt = 0; mt < 4; mt++) {
        int gr = bx*128 + wm*64 + mt*16 + lq;
        #pragma unroll
        for (int nt = 0; nt < 4; nt++) {
            int gc = by*128 + wn*32 + nt*8 + lr*2;
            float2 v0 = make_float2(acc[mt][nt][0] + bias[nt].x, acc[mt][nt][1] + bias[nt].y);
            float2 v1 = make_float2(acc[mt][nt][2] + bias[nt].x, acc[mt][nt][3] + bias[nt].y);
            *(float2*)&g_w[(size_t)gr*FD + gc]     = v0;
            *(float2*)&g_w[(size_t)(gr+8)*FD + gc] = v1;
        }
    }
}

// ---------------- node feature init ----------------
__global__ void k_init(const float* __restrict__ node_embed, const int* __restrict__ species) {
    int i = blockIdx.x*blockDim.x + threadIdx.x;
    if (i < NN*FD) {
        int n = i >> 9, idx = i & 511;
        g_fa[i] = (idx < 32) ? node_embed[species[n]*32 + idx] : 0.f;
    }
}

// ---------------- one message-passing layer ----------------
// block = 1 node, 128 threads; warp l owns angular channel l (dim = 2l+1).
// f layout per node: offset 32*l*l + c*(2l+1) + m.
template<int LVAL>
__device__ __forceinline__ void layer_warp(int t, int lane, int e0, int e1,
                                           const float* __restrict__ fp,
                                           const int* __restrict__ ei,
                                           const float* __restrict__ sw,
                                           const float* __restrict__ mw,
                                           const float* s_f, float* s_agg, float* s_new) {
    constexpr int dim = 2*LVAL + 1;
    constexpr int off = 32*LVAL*LVAL;
    constexpr int shoff = LVAL*LVAL;

    float acc[dim];
    #pragma unroll
    for (int m = 0; m < dim; m++) acc[m] = 0.f;

    int ii = e0;
    #pragma unroll 1
    for (; ii + 2 <= e1; ii += 2) {
        int ea = g_eid[ii], eb = g_eid[ii+1];
        float wa = g_w[(size_t)ea*FD + t*128 + LVAL*32 + lane];
        float wb = g_w[(size_t)eb*FD + t*128 + LVAL*32 + lane];
        float sa = fp[(size_t)ei[ea]*FD + lane];
        float sb = fp[(size_t)ei[eb]*FD + lane];
        float wsa = wa*sa, wsb = wb*sb;
        const float* pa = &g_sh[(size_t)ea*16 + shoff];
        const float* pb = &g_sh[(size_t)eb*16 + shoff];
        #pragma unroll
        for (int m = 0; m < dim; m++) acc[m] += wsa*pa[m] + wsb*pb[m];
    }
    if (ii < e1) {
        int e = g_eid[ii];
        float w = g_w[(size_t)e*FD + t*128 + LVAL*32 + lane];
        float s = fp[(size_t)ei[e]*FD + lane];
        float ws = w*s;
        const float* shp = &g_sh[(size_t)e*16 + shoff];
        #pragma unroll
        for (int m = 0; m < dim; m++) acc[m] += ws*shp[m];
    }
    #pragma unroll
    for (int m = 0; m < dim; m++) s_agg[off + lane*dim + m] = acc[m];
    __syncwarp();

    // einsum: new[d,m] = sum_c f[c,m]*sw[c,d] + agg[c,m]*mw[c,d]  (lane = d)
    // NOTE: s_f must be block-visible; caller syncs before this is valid — we
    // rely on the __syncthreads placed between s_f fill and the einsum below.
    float o[dim];
    #pragma unroll
    for (int m = 0; m < dim; m++) o[m] = 0.f;
    const float* swp = sw + (size_t)((t*4 + LVAL)*32)*32;
    const float* mwp = mw + (size_t)((t*4 + LVAL)*32)*32;
    #pragma unroll 4
    for (int c = 0; c < 32; c++) {
        float wsv = swp[c*32 + lane];
        float wmv = mwp[c*32 + lane];
        #pragma unroll
        for (int m = 0; m < dim; m++)
            o[m] += s_f[off + c*dim + m]*wsv + s_agg[off + c*dim + m]*wmv;
    }
    #pragma unroll
    for (int m = 0; m < dim; m++) s_new[off + lane*dim + m] = o[m];
}

__global__ void k_layer(int t,
                        const float* __restrict__ sw, const float* __restrict__ mw,
                        const float* __restrict__ gw, const int* __restrict__ ei,
                        float* __restrict__ outp) {
    const float* fp = (t == 1) ? g_fb : g_fa;
    float* fn = (t == 0) ? g_fb : ((t == 1) ? g_fa : outp);

    __shared__ float s_f[FD], s_agg[FD], s_new[FD], s_gate[32];
    int n = blockIdx.x;
    int tid = threadIdx.x, l = tid >> 5, lane = tid & 31;

    #pragma unroll
    for (int k = 0; k < 4; k++)
        s_f[tid + k*128] = fp[(size_t)n*FD + tid + k*128];

    int e0 = g_off[n], e1 = g_off[n+1];

    // gather into s_agg (own-warp section), needs no cross-warp data yet
    // einsum inside layer_warp reads s_f (all warps' writes) -> sync first.
    // structure: gather -> syncthreads -> einsum. Split template in two parts
    // would complicate; instead sync inside via shared staging:
    __syncthreads();   // s_f complete before any einsum read

    switch (l) {
        case 0: layer_warp<0>(t, lane, e0, e1, fp, ei, sw, mw, s_f, s_agg, s_new); break;
        case 1: layer_warp<1>(t, lane, e0, e1, fp, ei, sw, mw, s_f, s_agg, s_new); break;
        case 2: layer_warp<2>(t, lane, e0, e1, fp, ei, sw, mw, s_f, s_agg, s_new); break;
        default: layer_warp<3>(t, lane, e0, e1, fp, ei, sw, mw, s_f, s_agg, s_new); break;
    }
    __syncthreads();

    // gate from new0 (warp 0 wrote s_new[0..31])
    if (l == 0) {
        float g = 0.f;
        #pragma unroll 4
        for (int c = 0; c < 32; c++)
            g += s_new[c] * gw[(t*32 + c)*32 + lane];
        s_gate[lane] = 1.0f / (1.0f + expf(-g));
    }
    __syncthreads();

    // activation / gating + writeout
    #pragma unroll
    for (int k = 0; k < 4; k++) {
        int idx = tid + k*128;
        float v = s_new[idx];
        float outv;
        if (idx < 32) {
            outv = v / (1.0f + expf(-v));          // silu on l=0
        } else {
            int d;
            if (idx < 128)      d = (idx - 32) / 3;
            else if (idx < 288) d = (idx - 128) / 5;
            else                d = (idx - 288) / 7;
            outv = v * s_gate[d];
        }
        fn[(size_t)n*FD + idx] = outv;
    }
}

// ---------------- edge output ----------------
__global__ void k_edge_out(const int* __restrict__ ei, const float* __restrict__ nodef,
                           float* __restrict__ out) {
    __shared__ float s_g[32], s_sh[16], s_ew[128];
    int e = blockIdx.x, tid = threadIdx.x;
    int sn = ei[e], dn = ei[EE + e];
    if (tid < 32)
        s_g[tid] = nodef[(size_t)sn*FD + tid] + nodef[(size_t)dn*FD + tid];
    else if (tid < 48)
        s_sh[tid - 32] = g_sh[(size_t)e*16 + (tid - 32)];
    s_ew[tid] = g_w[(size_t)e*FD + 384 + tid];
    __syncthreads();

    float* orow = out + (size_t)(NN + e)*FD;
    #pragma unroll
    for (int k = 0; k < 4; k++) {
        int idx = tid + k*128;
        int l, c, m;
        if (idx < 32)       { l = 0; c = idx;       m = 0; }
        else if (idx < 128) { int r = idx - 32;  l = 1; c = r/3; m = r - 3*c; }
        else if (idx < 288) { int r = idx - 128; l = 2; c = r/5; m = r - 5*c; }
        else                { int r = idx - 288; l = 3; c = r/7; m = r - 7*c; }
        orow[idx] = s_ew[l*32 + c] * s_g[c] * s_sh[l*l + m];
    }
}

// ---------------- launch ----------------
extern "C" void kernel_launch(void* const* d_in, const int* in_sizes, int n_in,
                              void* d_out, int out_size) {
    const float* pos        = (const float*)d_in[0];
    const float* node_embed = (const float*)d_in[1];
    const float* rw1        = (const float*)d_in[2];
    const float* rb1        = (const float*)d_in[3];
    const float* rw2        = (const float*)d_in[4];
    const float* rb2        = (const float*)d_in[5];
    const float* self_w     = (const float*)d_in[6];
    const float* msg_w      = (const float*)d_in[7];
    const float* gate_w     = (const float*)d_in[8];
    const float* edge_w     = (const float*)d_in[9];
    const float* edge_b     = (const float*)d_in[10];
    const int*   species    = (const int*)d_in[11];
    const int*   ei         = (const int*)d_in[12];
    float* out = (float*)d_out;

    // CSR by dst
    k_zero_cnt<<<(NN+255)/256, 256>>>();
    k_hist<<<(EE+255)/256, 256>>>(ei);
    k_scan<<<1, 1024>>>();
    k_zero_cnt<<<(NN+255)/256, 256>>>();
    k_fill<<<(EE+255)/256, 256>>>(ei);

    // per-edge geometry, radial basis, hidden layer
    k_geom<<<EE/128, 256>>>(pos, rw1, rb1, ei);

    // second MLP layer -> [w_all | ew]  (tf32 tensor cores)
    dim3 gg(EE/128, 4);
    k_gemm<<<gg, 256>>>(rw2, edge_w, rb2, edge_b);

    // node features
    k_init<<<(NN*FD + 255)/256, 256>>>(node_embed, species);

    // 3 message-passing layers; last writes node rows of d_out directly
    for (int t = 0; t < 3; t++)
        k_layer<<<NN, 128>>>(t, self_w, msg_w, gate_w, ei, out);

    // edge rows of d_out
    k_edge_out<<<EE, 128>>>(ei, out, out);
}

// round 4
// speedup vs baseline: 1.2150x; 1.2150x over previous
#include <cuda_runtime.h>
#include <math.h>
#include <cstdint>

#define NN 10000
#define EE 160000
#define CC 32
#define NB 128
#define HH 64
#define FD 512   // C * (1+3+5+7)

typedef unsigned long long u64t;

// ---------------- scratch (device globals; no allocation) ----------------
__device__ float g_h[(size_t)EE*HH];     // 41 MB  : hidden per edge
__device__ float g_sh[(size_t)EE*16];    // 10 MB  : spherical harmonics per edge
__device__ float g_w[(size_t)EE*FD];     // 328 MB : [w_all(384) | ew(128)] per edge
__device__ float g_fa[(size_t)NN*FD];    // 20 MB  : node features buf A
__device__ float g_fb[(size_t)NN*FD];    // 20 MB  : node features buf B
__device__ int   g_cnt[NN];
__device__ int   g_cnt2[NN];
__device__ int   g_off[NN+1];
__device__ int   g_eid[EE];

// ---------------- packed fp32 helpers ----------------
__device__ __forceinline__ u64t pack2(float v) {
    u64t r; asm("mov.b64 %0, {%1, %1};" : "=l"(r) : "f"(v)); return r;
}
__device__ __forceinline__ u64t pack2two(float lo, float hi) {
    u64t r; asm("mov.b64 %0, {%1, %2};" : "=l"(r) : "f"(lo), "f"(hi)); return r;
}
__device__ __forceinline__ void unpack2(u64t v, float& lo, float& hi) {
    asm("mov.b64 {%0, %1}, %2;" : "=f"(lo), "=f"(hi) : "l"(v));
}
__device__ __forceinline__ void ffma2(u64t& d, u64t a, u64t b) {
    asm("fma.rn.f32x2 %0, %1, %2, %0;" : "+l"(d) : "l"(a), "l"(b));
}
__device__ __forceinline__ u64t fadd2(u64t a, u64t b) {
    u64t r; asm("add.rn.f32x2 %0, %1, %2;" : "=l"(r) : "l"(a), "l"(b)); return r;
}

// ---------------- CSR build ----------------
__global__ void k_zero() {
    int i = blockIdx.x*blockDim.x + threadIdx.x;
    if (i < NN) { g_cnt[i] = 0; g_cnt2[i] = 0; }
}

__global__ void k_hist(const int* __restrict__ ei) {
    int e = blockIdx.x*blockDim.x + threadIdx.x;
    if (e < EE) atomicAdd(&g_cnt[ei[EE + e]], 1);
}

__global__ void k_scan() {
    __shared__ int sdat[1024];
    __shared__ int carry;
    int tid = threadIdx.x;
    if (tid == 0) { carry = 0; g_off[0] = 0; }
    __syncthreads();
    for (int base = 0; base < NN; base += 1024) {
        int i = base + tid;
        int v = (i < NN) ? g_cnt[i] : 0;
        sdat[tid] = v;
        __syncthreads();
        for (int o = 1; o < 1024; o <<= 1) {
            int t = (tid >= o) ? sdat[tid - o] : 0;
            __syncthreads();
            sdat[tid] += t;
            __syncthreads();
        }
        int incl = sdat[tid] + carry;
        if (i < NN) g_off[i+1] = incl;
        __syncthreads();
        if (tid == 1023) carry = incl;
        __syncthreads();
    }
}

__global__ void k_fill(const int* __restrict__ ei) {
    int e = blockIdx.x*blockDim.x + threadIdx.x;
    if (e < EE) {
        int d = ei[EE + e];
        int p = atomicAdd(&g_cnt2[d], 1);
        g_eid[g_off[d] + p] = e;
    }
}

// ---------------- fused: geometry + sh + radial basis + MLP1 (f32x2) ----------------
// block = 128 edges, 256 threads; dynamic smem:
//   [0, 65536)       rb[k][e]   (128 x 128)
//   [65536, 98304)   b1[k][n]   (128 x 64)  = rw1
//   [98304, 98816)   su[128]
//   [98816, 99328)   ss[128]
#define GEOMH_SMEM 99328
__global__ void k_geomh(const float* __restrict__ pos, const float* __restrict__ rw1,
                        const float* __restrict__ rb1, const int* __restrict__ ei) {
    extern __shared__ char smem[];
    float* rb_s = (float*)smem;
    float* b1_s = (float*)(smem + 65536);
    float* su   = (float*)(smem + 98304);
    float* ss   = (float*)(smem + 98816);
    int tid = threadIdx.x;
    int eb = blockIdx.x*128;

    // phase A: geometry + spherical harmonics (threads 0..127, one edge each)
    if (tid < 128) {
        int e = eb + tid;
        int sn = ei[e], dn = ei[EE + e];
        float vx = pos[dn*3+0] - pos[sn*3+0];
        float vy = pos[dn*3+1] - pos[sn*3+1];
        float vz = pos[dn*3+2] - pos[sn*3+2];
        float r2 = vx*vx + vy*vy + vz*vz + 1e-12f;
        float r  = sqrtf(r2);
        float inv_r = 1.0f / r;
        float x = vx*inv_r, y = vy*inv_r, z = vz*inv_r;

        const float s3  = 1.7320508075688772f;
        const float s15 = 3.872983346207417f;
        const float s5h = 1.118033988749895f;
        const float s15h= 1.9364916731037085f;
        const float c1  = 2.091650066335189f;
        const float c2  = 10.246950765959598f;
        const float c3  = 1.6201851746019651f;
        const float c4  = 1.3228756555322954f;
        const float c5  = 5.123475382979799f;
        float4 q0 = make_float4(1.0f, s3*x, s3*y, s3*z);
        float4 q1 = make_float4(s15*x*y, s15*y*z, s5h*(3.0f*z*z - 1.0f), s15*x*z);
        float4 q2 = make_float4(s15h*(x*x - y*y), c1*y*(3.0f*x*x - y*y), c2*x*y*z,
                                c3*y*(5.0f*z*z - 1.0f));
        float4 q3 = make_float4(c4*(5.0f*z*z*z - 3.0f*z), c3*x*(5.0f*z*z - 1.0f),
                                c5*z*(x*x - y*y), c1*x*(x*x - 3.0f*y*y));
        float4* shp = (float4*)&g_sh[(size_t)e*16];
        shp[0] = q0; shp[1] = q1; shp[2] = q2; shp[3] = q3;

        float u = fminf(r * 0.2f, 1.0f);
        float env = 0.5f * (cospif(u) + 1.0f);
        su[tid] = u;
        ss[tid] = env * 0.6324555320336759f * inv_r;   // sqrt(2/RC)/r * env
    }
    // load rw1 -> b1 (8192 floats)
    {
        const float4* src = (const float4*)rw1;
        float4* dst = (float4*)b1_s;
        #pragma unroll
        for (int i = tid; i < 2048; i += 256) dst[i] = src[i];
    }
    __syncthreads();

    // phase B: radial basis rb[k][e]
    {
        int e = tid & 127, kh = tid >> 7;   // kh in {0,1}
        float u = su[e], sc = ss[e];
        #pragma unroll 4
        for (int j = 0; j < 64; j++) {
            int k = kh*64 + j;
            rb_s[k*128 + e] = sc * sinpif((float)(k+1) * u);
        }
    }
    __syncthreads();

    // phase C: h = silu(rb @ rw1 + rb1). C tile 128x64, thread tile 8e x 4n,
    // f32x2 packed along edge pairs.
    int ty = tid >> 4, tx = tid & 15;       // ty: 0..15 (e/8), tx: 0..15 (n/4)
    u64t acc[4][4];
    #pragma unroll
    for (int p = 0; p < 4; p++)
        #pragma unroll
        for (int c = 0; c < 4; c++) acc[p][c] = 0ull;

    #pragma unroll 4
    for (int k = 0; k < 128; k++) {
        u64t ap[4];
        #pragma unroll
        for (int p = 0; p < 4; p++)
            ap[p] = *(const u64t*)&rb_s[k*128 + ty*8 + 2*p];
        float4 bv = *(const float4*)&b1_s[k*64 + tx*4];
        u64t bp[4] = {pack2(bv.x), pack2(bv.y), pack2(bv.z), pack2(bv.w)};
        #pragma unroll
        for (int p = 0; p < 4; p++)
            #pragma unroll
            for (int c = 0; c < 4; c++)
                ffma2(acc[p][c], ap[p], bp[c]);
    }

    float4 bias = *(const float4*)&rb1[tx*4];
    float bb[4] = {bias.x, bias.y, bias.z, bias.w};
    #pragma unroll
    for (int p = 0; p < 4; p++) {
        float lo[4], hi[4];
        #pragma unroll
        for (int c = 0; c < 4; c++) unpack2(acc[p][c], lo[c], hi[c]);
        float4 vlo, vhi;
        float* plo = &vlo.x; float* phi = &vhi.x;
        #pragma unroll
        for (int c = 0; c < 4; c++) {
            float a = lo[c] + bb[c];
            float b = hi[c] + bb[c];
            plo[c] = a / (1.0f + expf(-a));
            phi[c] = b / (1.0f + expf(-b));
        }
        int e0 = eb + ty*8 + 2*p;
        *(float4*)&g_h[(size_t)e0*64 + tx*4]     = vlo;
        *(float4*)&g_h[(size_t)(e0+1)*64 + tx*4] = vhi;
    }
}

// ---------------- GEMM2 (f32x2): g_w = g_h (E x 64) @ [rw2|edge_w] (64 x 512) + bias ----
// BM=64, BN=128, BK=64 full. 256 threads, thread tile 4m x 8n (n packed in pairs).
// dyn smem: As_dup [64][64] float2 (32 KB) | Bs [64][128] float (32 KB)
#define GEMM_SMEM 65536
__global__ void k_gemm(const float* __restrict__ rw2, const float* __restrict__ edge_w,
                       const float* __restrict__ rb2, const float* __restrict__ edge_b) {
    extern __shared__ char smg[];
    float2* As = (float2*)smg;              // duplicated a values
    float*  Bs = (float*)(smg + 32768);
    int tid = threadIdx.x;
    int bx = blockIdx.x, by = blockIdx.y;

    #pragma unroll
    for (int i = tid; i < 4096; i += 256) {
        int row = i >> 6, k = i & 63;
        float v = g_h[(size_t)(bx*64 + row)*64 + k];
        As[i] = make_float2(v, v);
    }
    #pragma unroll
    for (int i = tid; i < 2048; i += 256) {
        int krow = i >> 5, c4 = i & 31;
        int jg = by*128 + c4*4;
        float4 v = (jg < 384) ? *(const float4*)&rw2[krow*384 + jg]
                              : *(const float4*)&edge_w[krow*128 + (jg - 384)];
        *(float4*)&Bs[krow*128 + c4*4] = v;
    }
    __syncthreads();

    int ty = tid >> 4, tx = tid & 15;       // rows ty*4..+3, cols tx*8..+7
    u64t acc[4][4];
    #pragma unroll
    for (int r = 0; r < 4; r++)
        #pragma unroll
        for (int c = 0; c < 4; c++) acc[r][c] = 0ull;

    #pragma unroll 8
    for (int k = 0; k < 64; k++) {
        u64t ap[4];
        #pragma unroll
        for (int r = 0; r < 4; r++)
            ap[r] = *(const u64t*)&As[(ty*4 + r)*64 + k];
        ulonglong2 B0 = *(const ulonglong2*)&Bs[k*128 + tx*8];
        ulonglong2 B1 = *(const ulonglong2*)&Bs[k*128 + tx*8 + 4];
        u64t bp[4] = {B0.x, B0.y, B1.x, B1.y};
        #pragma unroll
        for (int r = 0; r < 4; r++)
            #pragma unroll
            for (int c = 0; c < 4; c++)
                ffma2(acc[r][c], ap[r], bp[c]);
    }

    u64t bias[4];
    #pragma unroll
    for (int c = 0; c < 4; c++) {
        int jg = by*128 + tx*8 + c*2;
        float b0 = (jg   < 384) ? rb2[jg]   : edge_b[jg - 384];
        float b1 = (jg+1 < 384) ? rb2[jg+1] : edge_b[jg+1 - 384];
        bias[c] = pack2two(b0, b1);
    }
    #pragma unroll
    for (int r = 0; r < 4; r++) {
        size_t base = (size_t)(bx*64 + ty*4 + r)*FD + by*128 + tx*8;
        #pragma unroll
        for (int c = 0; c < 4; c++)
            *(u64t*)&g_w[base + c*2] = fadd2(acc[r][c], bias[c]);
    }
}

// ---------------- node feature init ----------------
__global__ void k_init(const float* __restrict__ node_embed, const int* __restrict__ species) {
    int i = blockIdx.x*blockDim.x + threadIdx.x;
    if (i < NN*FD) {
        int n = i >> 9, idx = i & 511;
        g_fa[i] = (idx < 32) ? node_embed[species[n]*32 + idx] : 0.f;
    }
}

// ---------------- one message-passing layer ----------------
template<int LVAL>
__device__ __forceinline__ void layer_warp(int t, int lane, int e0, int e1,
                                           const float* __restrict__ fp,
                                           const int* __restrict__ ei,
                                           const float* __restrict__ sw,
                                           const float* __restrict__ mw,
                                           const float* s_f, float* s_agg, float* s_new) {
    constexpr int dim = 2*LVAL + 1;
    constexpr int off = 32*LVAL*LVAL;
    constexpr int shoff = LVAL*LVAL;

    float acc[dim];
    #pragma unroll
    for (int m = 0; m < dim; m++) acc[m] = 0.f;

    int ii = e0;
    #pragma unroll 1
    for (; ii + 2 <= e1; ii += 2) {
        int ea = g_eid[ii], eb = g_eid[ii+1];
        float wa = g_w[(size_t)ea*FD + t*128 + LVAL*32 + lane];
        float wb = g_w[(size_t)eb*FD + t*128 + LVAL*32 + lane];
        float sa = fp[(size_t)ei[ea]*FD + lane];
        float sb = fp[(size_t)ei[eb]*FD + lane];
        float wsa = wa*sa, wsb = wb*sb;
        const float* pa = &g_sh[(size_t)ea*16 + shoff];
        const float* pb = &g_sh[(size_t)eb*16 + shoff];
        #pragma unroll
        for (int m = 0; m < dim; m++) acc[m] += wsa*pa[m] + wsb*pb[m];
    }
    if (ii < e1) {
        int e = g_eid[ii];
        float w = g_w[(size_t)e*FD + t*128 + LVAL*32 + lane];
        float s = fp[(size_t)ei[e]*FD + lane];
        float ws = w*s;
        const float* shp = &g_sh[(size_t)e*16 + shoff];
        #pragma unroll
        for (int m = 0; m < dim; m++) acc[m] += ws*shp[m];
    }
    #pragma unroll
    for (int m = 0; m < dim; m++) s_agg[off + lane*dim + m] = acc[m];
    __syncwarp();

    float o[dim];
    #pragma unroll
    for (int m = 0; m < dim; m++) o[m] = 0.f;
    const float* swp = sw + (size_t)((t*4 + LVAL)*32)*32;
    const float* mwp = mw + (size_t)((t*4 + LVAL)*32)*32;
    #pragma unroll 4
    for (int c = 0; c < 32; c++) {
        float wsv = swp[c*32 + lane];
        float wmv = mwp[c*32 + lane];
        #pragma unroll
        for (int m = 0; m < dim; m++)
            o[m] += s_f[off + c*dim + m]*wsv + s_agg[off + c*dim + m]*wmv;
    }
    #pragma unroll
    for (int m = 0; m < dim; m++) s_new[off + lane*dim + m] = o[m];
}

__global__ void k_layer(int t,
                        const float* __restrict__ sw, const float* __restrict__ mw,
                        const float* __restrict__ gw, const int* __restrict__ ei,
                        float* __restrict__ outp) {
    const float* fp = (t == 1) ? g_fb : g_fa;
    float* fn = (t == 0) ? g_fb : ((t == 1) ? g_fa : outp);

    __shared__ float s_f[FD], s_agg[FD], s_new[FD], s_gate[32];
    int n = blockIdx.x;
    int tid = threadIdx.x, l = tid >> 5, lane = tid & 31;

    #pragma unroll
    for (int k = 0; k < 4; k++)
        s_f[tid + k*128] = fp[(size_t)n*FD + tid + k*128];

    int e0 = g_off[n], e1 = g_off[n+1];
    __syncthreads();

    switch (l) {
        case 0: layer_warp<0>(t, lane, e0, e1, fp, ei, sw, mw, s_f, s_agg, s_new); break;
        case 1: layer_warp<1>(t, lane, e0, e1, fp, ei, sw, mw, s_f, s_agg, s_new); break;
        case 2: layer_warp<2>(t, lane, e0, e1, fp, ei, sw, mw, s_f, s_agg, s_new); break;
        default: layer_warp<3>(t, lane, e0, e1, fp, ei, sw, mw, s_f, s_agg, s_new); break;
    }
    __syncthreads();

    if (l == 0) {
        float g = 0.f;
        #pragma unroll 4
        for (int c = 0; c < 32; c++)
            g += s_new[c] * gw[(t*32 + c)*32 + lane];
        s_gate[lane] = 1.0f / (1.0f + expf(-g));
    }
    __syncthreads();

    #pragma unroll
    for (int k = 0; k < 4; k++) {
        int idx = tid + k*128;
        float v = s_new[idx];
        float outv;
        if (idx < 32) {
            outv = v / (1.0f + expf(-v));
        } else {
            int d;
            if (idx < 128)      d = (idx - 32) / 3;
            else if (idx < 288) d = (idx - 128) / 5;
            else                d = (idx - 288) / 7;
            outv = v * s_gate[d];
        }
        fn[(size_t)n*FD + idx] = outv;
    }
}

// ---------------- edge output ----------------
__global__ void k_edge_out(const int* __restrict__ ei, const float* __restrict__ nodef,
                           float* __restrict__ out) {
    __shared__ float s_g[32], s_sh[16], s_ew[128];
    int e = blockIdx.x, tid = threadIdx.x;
    int sn = ei[e], dn = ei[EE + e];
    if (tid < 32)
        s_g[tid] = nodef[(size_t)sn*FD + tid] + nodef[(size_t)dn*FD + tid];
    else if (tid < 48)
        s_sh[tid - 32] = g_sh[(size_t)e*16 + (tid - 32)];
    s_ew[tid] = g_w[(size_t)e*FD + 384 + tid];
    __syncthreads();

    float* orow = out + (size_t)(NN + e)*FD;
    #pragma unroll
    for (int k = 0; k < 4; k++) {
        int idx = tid + k*128;
        int l, c, m;
        if (idx < 32)       { l = 0; c = idx;       m = 0; }
        else if (idx < 128) { int r = idx - 32;  l = 1; c = r/3; m = r - 3*c; }
        else if (idx < 288) { int r = idx - 128; l = 2; c = r/5; m = r - 5*c; }
        else                { int r = idx - 288; l = 3; c = r/7; m = r - 7*c; }
        orow[idx] = s_ew[l*32 + c] * s_g[c] * s_sh[l*l + m];
    }
}

// ---------------- launch ----------------
extern "C" void kernel_launch(void* const* d_in, const int* in_sizes, int n_in,
                              void* d_out, int out_size) {
    const float* pos        = (const float*)d_in[0];
    const float* node_embed = (const float*)d_in[1];
    const float* rw1        = (const float*)d_in[2];
    const float* rb1        = (const float*)d_in[3];
    const float* rw2        = (const float*)d_in[4];
    const float* rb2        = (const float*)d_in[5];
    const float* self_w     = (const float*)d_in[6];
    const float* msg_w      = (const float*)d_in[7];
    const float* gate_w     = (const float*)d_in[8];
    const float* edge_w     = (const float*)d_in[9];
    const float* edge_b     = (const float*)d_in[10];
    const int*   species    = (const int*)d_in[11];
    const int*   ei         = (const int*)d_in[12];
    float* out = (float*)d_out;

    cudaFuncSetAttribute(k_geomh, cudaFuncAttributeMaxDynamicSharedMemorySize, GEOMH_SMEM);
    cudaFuncSetAttribute(k_gemm, cudaFuncAttributeMaxDynamicSharedMemorySize, GEMM_SMEM);

    // slot 0..2: CSR front half
    k_zero<<<(NN+255)/256, 256>>>();
    k_hist<<<(EE+255)/256, 256>>>(ei);
    k_scan<<<1, 1024>>>();

    // slot 3 (profiled): fused geometry + radial + MLP1
    k_geomh<<<EE/128, 256, GEOMH_SMEM>>>(pos, rw1, rb1, ei);

    // slot 4: CSR fill
    k_fill<<<(EE+255)/256, 256>>>(ei);

    // slot 5: GEMM2 (f32x2)
    dim3 gg(EE/64, 4);
    k_gemm<<<gg, 256, GEMM_SMEM>>>(rw2, edge_w, rb2, edge_b);

    // node features
    k_init<<<(NN*FD + 255)/256, 256>>>(node_embed, species);

    // 3 message-passing layers; last writes node rows of d_out directly
    for (int t = 0; t < 3; t++)
        k_layer<<<NN, 128>>>(t, self_w, msg_w, gate_w, ei, out);

    // edge rows of d_out
    k_edge_out<<<EE, 128>>>(ei, out, out);
}

// round 5
// speedup vs baseline: 1.5728x; 1.2945x over previous
#include <cuda_runtime.h>
#include <math.h>
#include <cstdint>

#define NN 10000
#define EE 160000
#define CC 32
#define NB 128
#define HH 64
#define FD 512   // C * (1+3+5+7)

typedef unsigned long long u64t;

// ---------------- scratch (device globals; no allocation) ----------------
__device__ float g_h[(size_t)EE*HH];     // 41 MB  : hidden per edge
__device__ float g_sh[(size_t)EE*16];    // 10 MB  : spherical harmonics per edge
__device__ float g_w[(size_t)EE*FD];     // 328 MB : [w_all(384) | ew(128)] per edge
__device__ float g_fa[(size_t)NN*FD];    // 20 MB  : node features buf A
__device__ float g_fb[(size_t)NN*FD];    // 20 MB  : node features buf B
__device__ float g_f0a[(size_t)NN*CC];   // 1.28 MB: compact f0 buf A
__device__ float g_f0b[(size_t)NN*CC];   // 1.28 MB: compact f0 buf B
__device__ int   g_cnt[NN];
__device__ int   g_cnt2[NN];
__device__ int   g_off[NN+1];
__device__ int   g_eid[EE];

// ---------------- packed fp32 helpers ----------------
__device__ __forceinline__ u64t pack2(float v) {
    u64t r; asm("mov.b64 %0, {%1, %1};" : "=l"(r) : "f"(v)); return r;
}
__device__ __forceinline__ u64t pack2two(float lo, float hi) {
    u64t r; asm("mov.b64 %0, {%1, %2};" : "=l"(r) : "f"(lo), "f"(hi)); return r;
}
__device__ __forceinline__ void unpack2(u64t v, float& lo, float& hi) {
    asm("mov.b64 {%0, %1}, %2;" : "=f"(lo), "=f"(hi) : "l"(v));
}
__device__ __forceinline__ void ffma2(u64t& d, u64t a, u64t b) {
    asm("fma.rn.f32x2 %0, %1, %2, %0;" : "+l"(d) : "l"(a), "l"(b));
}
__device__ __forceinline__ u64t fadd2(u64t a, u64t b) {
    u64t r; asm("add.rn.f32x2 %0, %1, %2;" : "=l"(r) : "l"(a), "l"(b)); return r;
}

// ---------------- CSR build ----------------
__global__ void k_zero() {
    int i = blockIdx.x*blockDim.x + threadIdx.x;
    if (i < NN) { g_cnt[i] = 0; g_cnt2[i] = 0; }
}

__global__ void k_hist(const int* __restrict__ ei) {
    int e = blockIdx.x*blockDim.x + threadIdx.x;
    if (e < EE) atomicAdd(&g_cnt[ei[EE + e]], 1);
}

__global__ void k_scan() {
    __shared__ int sdat[1024];
    __shared__ int carry;
    int tid = threadIdx.x;
    if (tid == 0) { carry = 0; g_off[0] = 0; }
    __syncthreads();
    for (int base = 0; base < NN; base += 1024) {
        int i = base + tid;
        int v = (i < NN) ? g_cnt[i] : 0;
        sdat[tid] = v;
        __syncthreads();
        for (int o = 1; o < 1024; o <<= 1) {
            int t = (tid >= o) ? sdat[tid - o] : 0;
            __syncthreads();
            sdat[tid] += t;
            __syncthreads();
        }
        int incl = sdat[tid] + carry;
        if (i < NN) g_off[i+1] = incl;
        __syncthreads();
        if (tid == 1023) carry = incl;
        __syncthreads();
    }
}

__global__ void k_fill(const int* __restrict__ ei) {
    int e = blockIdx.x*blockDim.x + threadIdx.x;
    if (e < EE) {
        int d = ei[EE + e];
        int p = atomicAdd(&g_cnt2[d], 1);
        g_eid[g_off[d] + p] = e;
    }
}

// ---------------- fused: geometry + sh + radial basis + MLP1 (f32x2) ----------------
#define GEOMH_SMEM 99328
__global__ void k_geomh(const float* __restrict__ pos, const float* __restrict__ rw1,
                        const float* __restrict__ rb1, const int* __restrict__ ei) {
    extern __shared__ char smem[];
    float* rb_s = (float*)smem;
    float* b1_s = (float*)(smem + 65536);
    float* su   = (float*)(smem + 98304);
    float* ss   = (float*)(smem + 98816);
    int tid = threadIdx.x;
    int eb = blockIdx.x*128;

    if (tid < 128) {
        int e = eb + tid;
        int sn = ei[e], dn = ei[EE + e];
        float vx = pos[dn*3+0] - pos[sn*3+0];
        float vy = pos[dn*3+1] - pos[sn*3+1];
        float vz = pos[dn*3+2] - pos[sn*3+2];
        float r2 = vx*vx + vy*vy + vz*vz + 1e-12f;
        float r  = sqrtf(r2);
        float inv_r = 1.0f / r;
        float x = vx*inv_r, y = vy*inv_r, z = vz*inv_r;

        const float s3  = 1.7320508075688772f;
        const float s15 = 3.872983346207417f;
        const float s5h = 1.118033988749895f;
        const float s15h= 1.9364916731037085f;
        const float c1  = 2.091650066335189f;
        const float c2  = 10.246950765959598f;
        const float c3  = 1.6201851746019651f;
        const float c4  = 1.3228756555322954f;
        const float c5  = 5.123475382979799f;
        float4 q0 = make_float4(1.0f, s3*x, s3*y, s3*z);
        float4 q1 = make_float4(s15*x*y, s15*y*z, s5h*(3.0f*z*z - 1.0f), s15*x*z);
        float4 q2 = make_float4(s15h*(x*x - y*y), c1*y*(3.0f*x*x - y*y), c2*x*y*z,
                                c3*y*(5.0f*z*z - 1.0f));
        float4 q3 = make_float4(c4*(5.0f*z*z*z - 3.0f*z), c3*x*(5.0f*z*z - 1.0f),
                                c5*z*(x*x - y*y), c1*x*(x*x - 3.0f*y*y));
        float4* shp = (float4*)&g_sh[(size_t)e*16];
        shp[0] = q0; shp[1] = q1; shp[2] = q2; shp[3] = q3;

        float u = fminf(r * 0.2f, 1.0f);
        float env = 0.5f * (cospif(u) + 1.0f);
        su[tid] = u;
        ss[tid] = env * 0.6324555320336759f * inv_r;
    }
    {
        const float4* src = (const float4*)rw1;
        float4* dst = (float4*)b1_s;
        #pragma unroll
        for (int i = tid; i < 2048; i += 256) dst[i] = src[i];
    }
    __syncthreads();

    {
        int e = tid & 127, kh = tid >> 7;
        float u = su[e], sc = ss[e];
        #pragma unroll 4
        for (int j = 0; j < 64; j++) {
            int k = kh*64 + j;
            rb_s[k*128 + e] = sc * sinpif((float)(k+1) * u);
        }
    }
    __syncthreads();

    int ty = tid >> 4, tx = tid & 15;
    u64t acc[4][4];
    #pragma unroll
    for (int p = 0; p < 4; p++)
        #pragma unroll
        for (int c = 0; c < 4; c++) acc[p][c] = 0ull;

    #pragma unroll 4
    for (int k = 0; k < 128; k++) {
        u64t ap[4];
        #pragma unroll
        for (int p = 0; p < 4; p++)
            ap[p] = *(const u64t*)&rb_s[k*128 + ty*8 + 2*p];
        float4 bv = *(const float4*)&b1_s[k*64 + tx*4];
        u64t bp[4] = {pack2(bv.x), pack2(bv.y), pack2(bv.z), pack2(bv.w)};
        #pragma unroll
        for (int p = 0; p < 4; p++)
            #pragma unroll
            for (int c = 0; c < 4; c++)
                ffma2(acc[p][c], ap[p], bp[c]);
    }

    float4 bias = *(const float4*)&rb1[tx*4];
    float bb[4] = {bias.x, bias.y, bias.z, bias.w};
    #pragma unroll
    for (int p = 0; p < 4; p++) {
        float lo[4], hi[4];
        #pragma unroll
        for (int c = 0; c < 4; c++) unpack2(acc[p][c], lo[c], hi[c]);
        float4 vlo, vhi;
        float* plo = &vlo.x; float* phi = &vhi.x;
        #pragma unroll
        for (int c = 0; c < 4; c++) {
            float a = lo[c] + bb[c];
            float b = hi[c] + bb[c];
            plo[c] = a / (1.0f + expf(-a));
            phi[c] = b / (1.0f + expf(-b));
        }
        int e0 = eb + ty*8 + 2*p;
        *(float4*)&g_h[(size_t)e0*64 + tx*4]     = vlo;
        *(float4*)&g_h[(size_t)(e0+1)*64 + tx*4] = vhi;
    }
}

// ---------------- GEMM2 (f32x2, balanced tiling) ----------------
// g_w = g_h (E x 64) @ [rw2|edge_w] (64 x 512) + bias
// BM=128, BN=128, BK=64. 256 threads = 16(my) x 16(nx); thread tile 8m x 8n.
// A stored in smem as packed f32x2 m-pairs: As2[mp][k], stride 65 u64.
// B stored scalar: Bs[k][n], stride 132 floats.
#define AST 65
#define BST 132
#define GEMM_SMEM (64*AST*8 + 64*BST*4)   // 33280 + 33792 = 67072
__global__ void k_gemm(const float* __restrict__ rw2, const float* __restrict__ edge_w,
                       const float* __restrict__ rb2, const float* __restrict__ edge_b) {
    extern __shared__ char smg[];
    u64t*  As2 = (u64t*)smg;
    float* Bs  = (float*)(smg + 64*AST*8);
    int tid = threadIdx.x;
    int bx = blockIdx.x, by = blockIdx.y;
    int eb = bx*128;

    // stage A: m-pairs packed. li over 1024: mp = li>>4 (0..63), kq = li&15
    #pragma unroll
    for (int p = 0; p < 4; p++) {
        int li = tid + p*256;
        int mp = li >> 4, kq = li & 15;
        float4 va = *(const float4*)&g_h[(size_t)(eb + 2*mp)*64 + kq*4];
        float4 vb = *(const float4*)&g_h[(size_t)(eb + 2*mp + 1)*64 + kq*4];
        u64t* dst = &As2[(size_t)0];
        int base = kq*4;
        dst[(base+0)*AST + mp] = pack2two(va.x, vb.x);
        dst[(base+1)*AST + mp] = pack2two(va.y, vb.y);
        dst[(base+2)*AST + mp] = pack2two(va.z, vb.z);
        dst[(base+3)*AST + mp] = pack2two(va.w, vb.w);
    }
    // stage B: li over 2048: k = li>>5, n4 = li&31
    #pragma unroll
    for (int p = 0; p < 8; p++) {
        int li = tid + p*256;
        int k = li >> 5, n4 = li & 31;
        int jg = by*128 + n4*4;
        float4 v = (jg < 384) ? *(const float4*)&rw2[k*384 + jg]
                              : *(const float4*)&edge_w[k*128 + (jg - 384)];
        *(float4*)&Bs[k*BST + n4*4] = v;
    }
    __syncthreads();

    int my = tid >> 4, nx = tid & 15;     // my: m-pairs my*4..+3 (rows my*8..+7); nx: cols nx*8..+7
    u64t acc[4][8];
    #pragma unroll
    for (int i = 0; i < 4; i++)
        #pragma unroll
        for (int n = 0; n < 8; n++) acc[i][n] = 0ull;

    #pragma unroll 8
    for (int k = 0; k < 64; k++) {
        u64t a[4];
        #pragma unroll
        for (int i = 0; i < 4; i++)
            a[i] = As2[k*AST + my*4 + i];
        float4 b0 = *(const float4*)&Bs[k*BST + nx*8];
        float4 b1 = *(const float4*)&Bs[k*BST + nx*8 + 4];
        u64t bp[8] = {pack2(b0.x), pack2(b0.y), pack2(b0.z), pack2(b0.w),
                      pack2(b1.x), pack2(b1.y), pack2(b1.z), pack2(b1.w)};
        #pragma unroll
        for (int i = 0; i < 4; i++)
            #pragma unroll
            for (int n = 0; n < 8; n++)
                ffma2(acc[i][n], a[i], bp[n]);
    }

    // bias
    float bj[8];
    #pragma unroll
    for (int n = 0; n < 8; n++) {
        int jg = by*128 + nx*8 + n;
        bj[n] = (jg < 384) ? rb2[jg] : edge_b[jg - 384];
    }

    // writeout: m-pair i -> rows eb + my*8 + 2i (+1)
    #pragma unroll
    for (int i = 0; i < 4; i++) {
        float lo[8], hi[8];
        #pragma unroll
        for (int n = 0; n < 8; n++) unpack2(acc[i][n], lo[n], hi[n]);
        size_t r0 = (size_t)(eb + my*8 + 2*i)*FD + by*128 + nx*8;
        size_t r1 = r0 + FD;
        float4 v0 = make_float4(lo[0]+bj[0], lo[1]+bj[1], lo[2]+bj[2], lo[3]+bj[3]);
        float4 v1 = make_float4(lo[4]+bj[4], lo[5]+bj[5], lo[6]+bj[6], lo[7]+bj[7]);
        float4 w0 = make_float4(hi[0]+bj[0], hi[1]+bj[1], hi[2]+bj[2], hi[3]+bj[3]);
        float4 w1 = make_float4(hi[4]+bj[4], hi[5]+bj[5], hi[6]+bj[6], hi[7]+bj[7]);
        *(float4*)&g_w[r0]     = v0;
        *(float4*)&g_w[r0 + 4] = v1;
        *(float4*)&g_w[r1]     = w0;
        *(float4*)&g_w[r1 + 4] = w1;
    }
}

// ---------------- node feature init ----------------
__global__ void k_init(const float* __restrict__ node_embed, const int* __restrict__ species) {
    int i = blockIdx.x*blockDim.x + threadIdx.x;
    if (i < NN*FD) {
        int n = i >> 9, idx = i & 511;
        float v = 0.f;
        if (idx < 32) {
            v = node_embed[species[n]*32 + idx];
            g_f0a[n*32 + idx] = v;
        }
        g_fa[i] = v;
    }
}

// ---------------- one message-passing layer ----------------
template<int LVAL>
__device__ __forceinline__ void layer_warp(int t, int lane, int e0, int e1,
                                           const float* __restrict__ f0p,
                                           const int* __restrict__ ei,
                                           const float* __restrict__ sw,
                                           const float* __restrict__ mw,
                                           const float* s_f, float* s_agg, float* s_new) {
    constexpr int dim = 2*LVAL + 1;
    constexpr int off = 32*LVAL*LVAL;
    constexpr int shoff = LVAL*LVAL;

    float acc[dim];
    #pragma unroll
    for (int m = 0; m < dim; m++) acc[m] = 0.f;

    int ii = e0;
    #pragma unroll 1
    for (; ii + 4 <= e1; ii += 4) {
        int ea = g_eid[ii],   eb = g_eid[ii+1];
        int ec = g_eid[ii+2], ed = g_eid[ii+3];
        float wa = g_w[(size_t)ea*FD + t*128 + LVAL*32 + lane];
        float wb = g_w[(size_t)eb*FD + t*128 + LVAL*32 + lane];
        float wc = g_w[(size_t)ec*FD + t*128 + LVAL*32 + lane];
        float wd = g_w[(size_t)ed*FD + t*128 + LVAL*32 + lane];
        float sa = f0p[ei[ea]*32 + lane];
        float sb = f0p[ei[eb]*32 + lane];
        float sc = f0p[ei[ec]*32 + lane];
        float sd = f0p[ei[ed]*32 + lane];
        float wsa = wa*sa, wsb = wb*sb, wsc = wc*sc, wsd = wd*sd;
        const float* pa = &g_sh[(size_t)ea*16 + shoff];
        const float* pb = &g_sh[(size_t)eb*16 + shoff];
        const float* pc = &g_sh[(size_t)ec*16 + shoff];
        const float* pd = &g_sh[(size_t)ed*16 + shoff];
        #pragma unroll
        for (int m = 0; m < dim; m++)
            acc[m] += wsa*pa[m] + wsb*pb[m] + wsc*pc[m] + wsd*pd[m];
    }
    #pragma unroll 1
    for (; ii < e1; ii++) {
        int e = g_eid[ii];
        float w = g_w[(size_t)e*FD + t*128 + LVAL*32 + lane];
        float s = f0p[ei[e]*32 + lane];
        float ws = w*s;
        const float* shp = &g_sh[(size_t)e*16 + shoff];
        #pragma unroll
        for (int m = 0; m < dim; m++) acc[m] += ws*shp[m];
    }
    #pragma unroll
    for (int m = 0; m < dim; m++) s_agg[off + lane*dim + m] = acc[m];
    __syncwarp();

    float o[dim];
    #pragma unroll
    for (int m = 0; m < dim; m++) o[m] = 0.f;
    const float* swp = sw + (size_t)((t*4 + LVAL)*32)*32;
    const float* mwp = mw + (size_t)((t*4 + LVAL)*32)*32;
    #pragma unroll 4
    for (int c = 0; c < 32; c++) {
        float wsv = swp[c*32 + lane];
        float wmv = mwp[c*32 + lane];
        #pragma unroll
        for (int m = 0; m < dim; m++)
            o[m] += s_f[off + c*dim + m]*wsv + s_agg[off + c*dim + m]*wmv;
    }
    #pragma unroll
    for (int m = 0; m < dim; m++) s_new[off + lane*dim + m] = o[m];
}

__global__ void k_layer(int t,
                        const float* __restrict__ sw, const float* __restrict__ mw,
                        const float* __restrict__ gw, const int* __restrict__ ei,
                        float* __restrict__ outp) {
    const float* fp  = (t == 1) ? g_fb : g_fa;
    float* fn        = (t == 0) ? g_fb : ((t == 1) ? g_fa : outp);
    const float* f0p = (t == 1) ? g_f0b : g_f0a;
    float* f0n       = (t == 1) ? g_f0a : g_f0b;

    __shared__ float s_f[FD], s_agg[FD], s_new[FD], s_gate[32];
    int n = blockIdx.x;
    int tid = threadIdx.x, l = tid >> 5, lane = tid & 31;

    #pragma unroll
    for (int k = 0; k < 4; k++)
        s_f[tid + k*128] = fp[(size_t)n*FD + tid + k*128];

    int e0 = g_off[n], e1 = g_off[n+1];
    __syncthreads();

    switch (l) {
        case 0: layer_warp<0>(t, lane, e0, e1, f0p, ei, sw, mw, s_f, s_agg, s_new); break;
        case 1: layer_warp<1>(t, lane, e0, e1, f0p, ei, sw, mw, s_f, s_agg, s_new); break;
        case 2: layer_warp<2>(t, lane, e0, e1, f0p, ei, sw, mw, s_f, s_agg, s_new); break;
        default: layer_warp<3>(t, lane, e0, e1, f0p, ei, sw, mw, s_f, s_agg, s_new); break;
    }
    __syncthreads();

    if (l == 0) {
        float g = 0.f;
        #pragma unroll 4
        for (int c = 0; c < 32; c++)
            g += s_new[c] * gw[(t*32 + c)*32 + lane];
        s_gate[lane] = 1.0f / (1.0f + expf(-g));
    }
    __syncthreads();

    #pragma unroll
    for (int k = 0; k < 4; k++) {
        int idx = tid + k*128;
        float v = s_new[idx];
        float outv;
        if (idx < 32) {
            outv = v / (1.0f + expf(-v));
            f0n[n*32 + idx] = outv;
        } else {
            int d;
            if (idx < 128)      d = (idx - 32) / 3;
            else if (idx < 288) d = (idx - 128) / 5;
            else                d = (idx - 288) / 7;
            outv = v * s_gate[d];
        }
        fn[(size_t)n*FD + idx] = outv;
    }
}

// ---------------- edge output: 2 edges per 256-thread block, float4 stores ----------------
__global__ void k_edge_out(const int* __restrict__ ei, float* __restrict__ out) {
    __shared__ float s_g[2][32], s_sh[2][16], s_ew[2][128];
    int tid = threadIdx.x;
    int half = tid >> 7, t = tid & 127;
    int e = blockIdx.x*2 + half;
    int sn = ei[e], dn = ei[EE + e];
    if (t < 32)
        s_g[half][t] = g_f0b[sn*32 + t] + g_f0b[dn*32 + t];
    else if (t < 48)
        s_sh[half][t - 32] = g_sh[(size_t)e*16 + (t - 32)];
    s_ew[half][t] = g_w[(size_t)e*FD + 384 + t];
    __syncthreads();

    float* orow = out + (size_t)(NN + e)*FD;
    int idx0 = t*4;
    float4 v;
    float* pv = &v.x;
    #pragma unroll
    for (int j = 0; j < 4; j++) {
        int idx = idx0 + j;
        int l, c, m;
        if (idx < 32)       { l = 0; c = idx;       m = 0; }
        else if (idx < 128) { int r = idx - 32;  l = 1; c = r/3; m = r - 3*c; }
        else if (idx < 288) { int r = idx - 128; l = 2; c = r/5; m = r - 5*c; }
        else                { int r = idx - 288; l = 3; c = r/7; m = r - 7*c; }
        pv[j] = s_ew[half][l*32 + c] * s_g[half][c] * s_sh[half][l*l + m];
    }
    *(float4*)&orow[idx0] = v;
}

// ---------------- launch ----------------
extern "C" void kernel_launch(void* const* d_in, const int* in_sizes, int n_in,
                              void* d_out, int out_size) {
    const float* pos        = (const float*)d_in[0];
    const float* node_embed = (const float*)d_in[1];
    const float* rw1        = (const float*)d_in[2];
    const float* rb1        = (const float*)d_in[3];
    const float* rw2        = (const float*)d_in[4];
    const float* rb2        = (const float*)d_in[5];
    const float* self_w     = (const float*)d_in[6];
    const float* msg_w      = (const float*)d_in[7];
    const float* gate_w     = (const float*)d_in[8];
    const float* edge_w     = (const float*)d_in[9];
    const float* edge_b     = (const float*)d_in[10];
    const int*   species    = (const int*)d_in[11];
    const int*   ei         = (const int*)d_in[12];
    float* out = (float*)d_out;

    cudaFuncSetAttribute(k_geomh, cudaFuncAttributeMaxDynamicSharedMemorySize, GEOMH_SMEM);
    cudaFuncSetAttribute(k_gemm, cudaFuncAttributeMaxDynamicSharedMemorySize, GEMM_SMEM);

    // slot 0..2: CSR front half
    k_zero<<<(NN+255)/256, 256>>>();
    k_hist<<<(EE+255)/256, 256>>>(ei);
    k_scan<<<1, 1024>>>();

    // slot 3 (profiled): fused geometry + radial + MLP1
    k_geomh<<<EE/128, 256, GEOMH_SMEM>>>(pos, rw1, rb1, ei);

    // slot 4: CSR fill
    k_fill<<<(EE+255)/256, 256>>>(ei);

    // slot 5: GEMM2 (f32x2, balanced)
    dim3 gg(EE/128, 4);
    k_gemm<<<gg, 256, GEMM_SMEM>>>(rw2, edge_w, rb2, edge_b);

    // node features
    k_init<<<(NN*FD + 255)/256, 256>>>(node_embed, species);

    // 3 message-passing layers; last writes node rows of d_out directly
    for (int t = 0; t < 3; t++)
        k_layer<<<NN, 128>>>(t, self_w, msg_w, gate_w, ei, out);

    // edge rows of d_out
    k_edge_out<<<EE/2, 256>>>(ei, out);
}

// round 6
// speedup vs baseline: 1.5958x; 1.0147x over previous
#include <cuda_runtime.h>
#include <math.h>
#include <cstdint>

#define NN 10000
#define EE 160000
#define CC 32
#define NB 128
#define HH 64
#define FD 512   // C * (1+3+5+7)

typedef unsigned long long u64t;

// ---------------- scratch (device globals; no allocation) ----------------
__device__ float g_h[(size_t)EE*HH];      // 41 MB  : hidden per edge
__device__ float g_sh[(size_t)EE*16];     // 10 MB  : sph harmonics, edge order (edge_out)
__device__ float g_sh2[(size_t)EE*16];    // 10 MB  : sph harmonics, CSR order (layers)
__device__ float g_wall[(size_t)EE*384];  // 246 MB : layer weights, CSR order
__device__ float g_ew[(size_t)EE*128];    // 82 MB  : edge-out weights, edge order
__device__ float g_fa[(size_t)NN*FD];     // 20 MB  : node features buf A
__device__ float g_fb[(size_t)NN*FD];     // 20 MB  : node features buf B
__device__ float g_f0a[(size_t)NN*CC];    // 1.28 MB: compact f0 buf A
__device__ float g_f0b[(size_t)NN*CC];    // 1.28 MB: compact f0 buf B
__device__ int   g_cnt[NN];
__device__ int   g_cnt2[NN];
__device__ int   g_off[NN+1];
__device__ int   g_slot[EE];              // edge -> CSR position
__device__ int   g_src[EE];               // CSR position -> src node

// ---------------- packed fp32 helpers ----------------
__device__ __forceinline__ u64t pack2(float v) {
    u64t r; asm("mov.b64 %0, {%1, %1};" : "=l"(r) : "f"(v)); return r;
}
__device__ __forceinline__ u64t pack2two(float lo, float hi) {
    u64t r; asm("mov.b64 %0, {%1, %2};" : "=l"(r) : "f"(lo), "f"(hi)); return r;
}
__device__ __forceinline__ void unpack2(u64t v, float& lo, float& hi) {
    asm("mov.b64 {%0, %1}, %2;" : "=f"(lo), "=f"(hi) : "l"(v));
}
__device__ __forceinline__ void ffma2(u64t& d, u64t a, u64t b) {
    asm("fma.rn.f32x2 %0, %1, %2, %0;" : "+l"(d) : "l"(a), "l"(b));
}

// ---------------- CSR build ----------------
__global__ void k_zero() {
    int i = blockIdx.x*blockDim.x + threadIdx.x;
    if (i < NN) { g_cnt[i] = 0; g_cnt2[i] = 0; }
}

__global__ void k_hist(const int* __restrict__ ei) {
    int e = blockIdx.x*blockDim.x + threadIdx.x;
    if (e < EE) atomicAdd(&g_cnt[ei[EE + e]], 1);
}

__global__ void k_scan() {
    __shared__ int sdat[1024];
    __shared__ int carry;
    int tid = threadIdx.x;
    if (tid == 0) { carry = 0; g_off[0] = 0; }
    __syncthreads();
    for (int base = 0; base < NN; base += 1024) {
        int i = base + tid;
        int v = (i < NN) ? g_cnt[i] : 0;
        sdat[tid] = v;
        __syncthreads();
        for (int o = 1; o < 1024; o <<= 1) {
            int t = (tid >= o) ? sdat[tid - o] : 0;
            __syncthreads();
            sdat[tid] += t;
            __syncthreads();
        }
        int incl = sdat[tid] + carry;
        if (i < NN) g_off[i+1] = incl;
        __syncthreads();
        if (tid == 1023) carry = incl;
        __syncthreads();
    }
}

__global__ void k_fill(const int* __restrict__ ei) {
    int e = blockIdx.x*blockDim.x + threadIdx.x;
    if (e < EE) {
        int d = ei[EE + e];
        int p = atomicAdd(&g_cnt2[d], 1);
        int slot = g_off[d] + p;
        g_slot[e] = slot;
        g_src[slot] = ei[e];
    }
}

// ---------------- fused: geometry + sh + radial basis + MLP1 (f32x2) ----------------
#define GEOMH_SMEM 99328
__global__ void k_geomh(const float* __restrict__ pos, const float* __restrict__ rw1,
                        const float* __restrict__ rb1, const int* __restrict__ ei) {
    extern __shared__ char smem[];
    float* rb_s = (float*)smem;
    float* b1_s = (float*)(smem + 65536);
    float* su   = (float*)(smem + 98304);
    float* ss   = (float*)(smem + 98816);
    int tid = threadIdx.x;
    int eb = blockIdx.x*128;

    if (tid < 128) {
        int e = eb + tid;
        int sn = ei[e], dn = ei[EE + e];
        float vx = pos[dn*3+0] - pos[sn*3+0];
        float vy = pos[dn*3+1] - pos[sn*3+1];
        float vz = pos[dn*3+2] - pos[sn*3+2];
        float r2 = vx*vx + vy*vy + vz*vz + 1e-12f;
        float r  = sqrtf(r2);
        float inv_r = 1.0f / r;
        float x = vx*inv_r, y = vy*inv_r, z = vz*inv_r;

        const float s3  = 1.7320508075688772f;
        const float s15 = 3.872983346207417f;
        const float s5h = 1.118033988749895f;
        const float s15h= 1.9364916731037085f;
        const float c1  = 2.091650066335189f;
        const float c2  = 10.246950765959598f;
        const float c3  = 1.6201851746019651f;
        const float c4  = 1.3228756555322954f;
        const float c5  = 5.123475382979799f;
        float4 q0 = make_float4(1.0f, s3*x, s3*y, s3*z);
        float4 q1 = make_float4(s15*x*y, s15*y*z, s5h*(3.0f*z*z - 1.0f), s15*x*z);
        float4 q2 = make_float4(s15h*(x*x - y*y), c1*y*(3.0f*x*x - y*y), c2*x*y*z,
                                c3*y*(5.0f*z*z - 1.0f));
        float4 q3 = make_float4(c4*(5.0f*z*z*z - 3.0f*z), c3*x*(5.0f*z*z - 1.0f),
                                c5*z*(x*x - y*y), c1*x*(x*x - 3.0f*y*y));
        float4* shp = (float4*)&g_sh[(size_t)e*16];
        shp[0] = q0; shp[1] = q1; shp[2] = q2; shp[3] = q3;
        int slot = g_slot[e];
        float4* shp2 = (float4*)&g_sh2[(size_t)slot*16];
        shp2[0] = q0; shp2[1] = q1; shp2[2] = q2; shp2[3] = q3;

        float u = fminf(r * 0.2f, 1.0f);
        float env = 0.5f * (cospif(u) + 1.0f);
        su[tid] = u;
        ss[tid] = env * 0.6324555320336759f * inv_r;
    }
    {
        const float4* src = (const float4*)rw1;
        float4* dst = (float4*)b1_s;
        #pragma unroll
        for (int i = tid; i < 2048; i += 256) dst[i] = src[i];
    }
    __syncthreads();

    {
        int e = tid & 127, kh = tid >> 7;
        float u = su[e], sc = ss[e];
        #pragma unroll 4
        for (int j = 0; j < 64; j++) {
            int k = kh*64 + j;
            rb_s[k*128 + e] = sc * sinpif((float)(k+1) * u);
        }
    }
    __syncthreads();

    int ty = tid >> 4, tx = tid & 15;
    u64t acc[4][4];
    #pragma unroll
    for (int p = 0; p < 4; p++)
        #pragma unroll
        for (int c = 0; c < 4; c++) acc[p][c] = 0ull;

    #pragma unroll 4
    for (int k = 0; k < 128; k++) {
        u64t ap[4];
        #pragma unroll
        for (int p = 0; p < 4; p++)
            ap[p] = *(const u64t*)&rb_s[k*128 + ty*8 + 2*p];
        float4 bv = *(const float4*)&b1_s[k*64 + tx*4];
        u64t bp[4] = {pack2(bv.x), pack2(bv.y), pack2(bv.z), pack2(bv.w)};
        #pragma unroll
        for (int p = 0; p < 4; p++)
            #pragma unroll
            for (int c = 0; c < 4; c++)
                ffma2(acc[p][c], ap[p], bp[c]);
    }

    float4 bias = *(const float4*)&rb1[tx*4];
    float bb[4] = {bias.x, bias.y, bias.z, bias.w};
    #pragma unroll
    for (int p = 0; p < 4; p++) {
        float lo[4], hi[4];
        #pragma unroll
        for (int c = 0; c < 4; c++) unpack2(acc[p][c], lo[c], hi[c]);
        float4 vlo, vhi;
        float* plo = &vlo.x; float* phi = &vhi.x;
        #pragma unroll
        for (int c = 0; c < 4; c++) {
            float a = lo[c] + bb[c];
            float b = hi[c] + bb[c];
            plo[c] = a / (1.0f + expf(-a));
            phi[c] = b / (1.0f + expf(-b));
        }
        int e0 = eb + ty*8 + 2*p;
        *(float4*)&g_h[(size_t)e0*64 + tx*4]     = vlo;
        *(float4*)&g_h[(size_t)(e0+1)*64 + tx*4] = vhi;
    }
}

// ---------------- GEMM2 (f32x2, balanced tiling, permuted writeout) ----------------
// BM=128, BN=128, BK=64. 256 threads = 16(my) x 16(nx); thread tile 8m x 8n.
// by<3 -> w_all cols (CSR-permuted rows); by==3 -> ew cols (edge-ordered rows).
#define AST 65
#define BST 132
#define GEMM_SMEM (64*AST*8 + 64*BST*4)   // 67072
__global__ void k_gemm(const float* __restrict__ rw2, const float* __restrict__ edge_w,
                       const float* __restrict__ rb2, const float* __restrict__ edge_b) {
    extern __shared__ char smg[];
    u64t*  As2 = (u64t*)smg;
    float* Bs  = (float*)(smg + 64*AST*8);
    int tid = threadIdx.x;
    int bx = blockIdx.x, by = blockIdx.y;
    int eb = bx*128;

    #pragma unroll
    for (int p = 0; p < 4; p++) {
        int li = tid + p*256;
        int mp = li >> 4, kq = li & 15;
        float4 va = *(const float4*)&g_h[(size_t)(eb + 2*mp)*64 + kq*4];
        float4 vb = *(const float4*)&g_h[(size_t)(eb + 2*mp + 1)*64 + kq*4];
        int base = kq*4;
        As2[(base+0)*AST + mp] = pack2two(va.x, vb.x);
        As2[(base+1)*AST + mp] = pack2two(va.y, vb.y);
        As2[(base+2)*AST + mp] = pack2two(va.z, vb.z);
        As2[(base+3)*AST + mp] = pack2two(va.w, vb.w);
    }
    #pragma unroll
    for (int p = 0; p < 8; p++) {
        int li = tid + p*256;
        int k = li >> 5, n4 = li & 31;
        int jg = by*128 + n4*4;
        float4 v = (jg < 384) ? *(const float4*)&rw2[k*384 + jg]
                              : *(const float4*)&edge_w[k*128 + (jg - 384)];
        *(float4*)&Bs[k*BST + n4*4] = v;
    }
    __syncthreads();

    int my = tid >> 4, nx = tid & 15;
    u64t acc[4][8];
    #pragma unroll
    for (int i = 0; i < 4; i++)
        #pragma unroll
        for (int n = 0; n < 8; n++) acc[i][n] = 0ull;

    #pragma unroll 8
    for (int k = 0; k < 64; k++) {
        u64t a[4];
        #pragma unroll
        for (int i = 0; i < 4; i++)
            a[i] = As2[k*AST + my*4 + i];
        float4 b0 = *(const float4*)&Bs[k*BST + nx*8];
        float4 b1 = *(const float4*)&Bs[k*BST + nx*8 + 4];
        u64t bp[8] = {pack2(b0.x), pack2(b0.y), pack2(b0.z), pack2(b0.w),
                      pack2(b1.x), pack2(b1.y), pack2(b1.z), pack2(b1.w)};
        #pragma unroll
        for (int i = 0; i < 4; i++)
            #pragma unroll
            for (int n = 0; n < 8; n++)
                ffma2(acc[i][n], a[i], bp[n]);
    }

    float bj[8];
    #pragma unroll
    for (int n = 0; n < 8; n++) {
        int jg = by*128 + nx*8 + n;
        bj[n] = (jg < 384) ? rb2[jg] : edge_b[jg - 384];
    }

    #pragma unroll
    for (int i = 0; i < 4; i++) {
        float lo[8], hi[8];
        #pragma unroll
        for (int n = 0; n < 8; n++) unpack2(acc[i][n], lo[n], hi[n]);
        int er0 = eb + my*8 + 2*i;
        size_t r0, r1;
        if (by < 3) {
            r0 = (size_t)g_slot[er0]*384     + by*128 + nx*8;
            r1 = (size_t)g_slot[er0 + 1]*384 + by*128 + nx*8;
        } else {
            r0 = (size_t)er0*128       + nx*8;
            r1 = (size_t)(er0 + 1)*128 + nx*8;
        }
        float* dst = (by < 3) ? g_wall : g_ew;
        float4 v0 = make_float4(lo[0]+bj[0], lo[1]+bj[1], lo[2]+bj[2], lo[3]+bj[3]);
        float4 v1 = make_float4(lo[4]+bj[4], lo[5]+bj[5], lo[6]+bj[6], lo[7]+bj[7]);
        float4 w0 = make_float4(hi[0]+bj[0], hi[1]+bj[1], hi[2]+bj[2], hi[3]+bj[3]);
        float4 w1 = make_float4(hi[4]+bj[4], hi[5]+bj[5], hi[6]+bj[6], hi[7]+bj[7]);
        *(float4*)&dst[r0]     = v0;
        *(float4*)&dst[r0 + 4] = v1;
        *(float4*)&dst[r1]     = w0;
        *(float4*)&dst[r1 + 4] = w1;
    }
}

// ---------------- node feature init ----------------
__global__ void k_init(const float* __restrict__ node_embed, const int* __restrict__ species) {
    int i = blockIdx.x*blockDim.x + threadIdx.x;
    if (i < NN*FD) {
        int n = i >> 9, idx = i & 511;
        float v = 0.f;
        if (idx < 32) {
            v = node_embed[species[n]*32 + idx];
            g_f0a[n*32 + idx] = v;
        }
        g_fa[i] = v;
    }
}

// ---------------- one message-passing layer (streaming gather) ----------------
template<int LVAL>
__device__ __forceinline__ void layer_warp(int t, int lane, int e0, int e1,
                                           const float* __restrict__ f0p,
                                           const float* __restrict__ sw,
                                           const float* __restrict__ mw,
                                           const float* s_f, float* s_agg, float* s_new) {
    constexpr int dim = 2*LVAL + 1;
    constexpr int off = 32*LVAL*LVAL;
    constexpr int shoff = LVAL*LVAL;
    const int wcol = t*128 + LVAL*32 + lane;

    float acc[dim];
    #pragma unroll
    for (int m = 0; m < dim; m++) acc[m] = 0.f;

    int ii = e0;
    #pragma unroll 1
    for (; ii + 4 <= e1; ii += 4) {
        float wa = g_wall[(size_t)(ii  )*384 + wcol];
        float wb = g_wall[(size_t)(ii+1)*384 + wcol];
        float wc = g_wall[(size_t)(ii+2)*384 + wcol];
        float wd = g_wall[(size_t)(ii+3)*384 + wcol];
        float sa = f0p[g_src[ii  ]*32 + lane];
        float sb = f0p[g_src[ii+1]*32 + lane];
        float sc = f0p[g_src[ii+2]*32 + lane];
        float sd = f0p[g_src[ii+3]*32 + lane];
        float wsa = wa*sa, wsb = wb*sb, wsc = wc*sc, wsd = wd*sd;
        const float* pa = &g_sh2[(size_t)(ii  )*16 + shoff];
        const float* pb = &g_sh2[(size_t)(ii+1)*16 + shoff];
        const float* pc = &g_sh2[(size_t)(ii+2)*16 + shoff];
        const float* pd = &g_sh2[(size_t)(ii+3)*16 + shoff];
        #pragma unroll
        for (int m = 0; m < dim; m++)
            acc[m] += wsa*pa[m] + wsb*pb[m] + wsc*pc[m] + wsd*pd[m];
    }
    #pragma unroll 1
    for (; ii < e1; ii++) {
        float w = g_wall[(size_t)ii*384 + wcol];
        float s = f0p[g_src[ii]*32 + lane];
        float ws = w*s;
        const float* shp = &g_sh2[(size_t)ii*16 + shoff];
        #pragma unroll
        for (int m = 0; m < dim; m++) acc[m] += ws*shp[m];
    }
    #pragma unroll
    for (int m = 0; m < dim; m++) s_agg[off + lane*dim + m] = acc[m];
    __syncwarp();

    float o[dim];
    #pragma unroll
    for (int m = 0; m < dim; m++) o[m] = 0.f;
    const float* swp = sw + (size_t)((t*4 + LVAL)*32)*32;
    const float* mwp = mw + (size_t)((t*4 + LVAL)*32)*32;
    #pragma unroll 4
    for (int c = 0; c < 32; c++) {
        float wsv = swp[c*32 + lane];
        float wmv = mwp[c*32 + lane];
        #pragma unroll
        for (int m = 0; m < dim; m++)
            o[m] += s_f[off + c*dim + m]*wsv + s_agg[off + c*dim + m]*wmv;
    }
    #pragma unroll
    for (int m = 0; m < dim; m++) s_new[off + lane*dim + m] = o[m];
}

__global__ void k_layer(int t,
                        const float* __restrict__ sw, const float* __restrict__ mw,
                        const float* __restrict__ gw,
                        float* __restrict__ outp) {
    const float* fp  = (t == 1) ? g_fb : g_fa;
    float* fn        = (t == 0) ? g_fb : ((t == 1) ? g_fa : outp);
    const float* f0p = (t == 1) ? g_f0b : g_f0a;
    float* f0n       = (t == 1) ? g_f0a : g_f0b;

    __shared__ float s_f[FD], s_agg[FD], s_new[FD], s_gate[32];
    int n = blockIdx.x;
    int tid = threadIdx.x, l = tid >> 5, lane = tid & 31;

    #pragma unroll
    for (int k = 0; k < 4; k++)
        s_f[tid + k*128] = fp[(size_t)n*FD + tid + k*128];

    int e0 = g_off[n], e1 = g_off[n+1];
    __syncthreads();

    switch (l) {
        case 0: layer_warp<0>(t, lane, e0, e1, f0p, sw, mw, s_f, s_agg, s_new); break;
        case 1: layer_warp<1>(t, lane, e0, e1, f0p, sw, mw, s_f, s_agg, s_new); break;
        case 2: layer_warp<2>(t, lane, e0, e1, f0p, sw, mw, s_f, s_agg, s_new); break;
        default: layer_warp<3>(t, lane, e0, e1, f0p, sw, mw, s_f, s_agg, s_new); break;
    }
    __syncthreads();

    if (l == 0) {
        float g = 0.f;
        #pragma unroll 4
        for (int c = 0; c < 32; c++)
            g += s_new[c] * gw[(t*32 + c)*32 + lane];
        s_gate[lane] = 1.0f / (1.0f + expf(-g));
    }
    __syncthreads();

    #pragma unroll
    for (int k = 0; k < 4; k++) {
        int idx = tid + k*128;
        float v = s_new[idx];
        float outv;
        if (idx < 32) {
            outv = v / (1.0f + expf(-v));
            f0n[n*32 + idx] = outv;
        } else {
            int d;
            if (idx < 128)      d = (idx - 32) / 3;
            else if (idx < 288) d = (idx - 128) / 5;
            else                d = (idx - 288) / 7;
            outv = v * s_gate[d];
        }
        fn[(size_t)n*FD + idx] = outv;
    }
}

// ---------------- edge output: 2 edges per 256-thread block, float4 stores ----------------
__global__ void k_edge_out(const int* __restrict__ ei, float* __restrict__ out) {
    __shared__ float s_g[2][32], s_sh[2][16], s_ew[2][128];
    int tid = threadIdx.x;
    int half = tid >> 7, t = tid & 127;
    int e = blockIdx.x*2 + half;
    int sn = ei[e], dn = ei[EE + e];
    if (t < 32)
        s_g[half][t] = g_f0b[sn*32 + t] + g_f0b[dn*32 + t];
    else if (t < 48)
        s_sh[half][t - 32] = g_sh[(size_t)e*16 + (t - 32)];
    s_ew[half][t] = g_ew[(size_t)e*128 + t];
    __syncthreads();

    float* orow = out + (size_t)(NN + e)*FD;
    int idx0 = t*4;
    float4 v;
    float* pv = &v.x;
    #pragma unroll
    for (int j = 0; j < 4; j++) {
        int idx = idx0 + j;
        int l, c, m;
        if (idx < 32)       { l = 0; c = idx;       m = 0; }
        else if (idx < 128) { int r = idx - 32;  l = 1; c = r/3; m = r - 3*c; }
        else if (idx < 288) { int r = idx - 128; l = 2; c = r/5; m = r - 5*c; }
        else                { int r = idx - 288; l = 3; c = r/7; m = r - 7*c; }
        pv[j] = s_ew[half][l*32 + c] * s_g[half][c] * s_sh[half][l*l + m];
    }
    *(float4*)&orow[idx0] = v;
}

// ---------------- launch ----------------
extern "C" void kernel_launch(void* const* d_in, const int* in_sizes, int n_in,
                              void* d_out, int out_size) {
    const float* pos        = (const float*)d_in[0];
    const float* node_embed = (const float*)d_in[1];
    const float* rw1        = (const float*)d_in[2];
    const float* rb1        = (const float*)d_in[3];
    const float* rw2        = (const float*)d_in[4];
    const float* rb2        = (const float*)d_in[5];
    const float* self_w     = (const float*)d_in[6];
    const float* msg_w      = (const float*)d_in[7];
    const float* gate_w     = (const float*)d_in[8];
    const float* edge_w     = (const float*)d_in[9];
    const float* edge_b     = (const float*)d_in[10];
    const int*   species    = (const int*)d_in[11];
    const int*   ei         = (const int*)d_in[12];
    float* out = (float*)d_out;

    cudaFuncSetAttribute(k_geomh, cudaFuncAttributeMaxDynamicSharedMemorySize, GEOMH_SMEM);
    cudaFuncSetAttribute(k_gemm, cudaFuncAttributeMaxDynamicSharedMemorySize, GEMM_SMEM);

    // CSR (slot/src permutation must exist before geomh/gemm)
    k_zero<<<(NN+255)/256, 256>>>();
    k_hist<<<(EE+255)/256, 256>>>(ei);
    k_scan<<<1, 1024>>>();
    k_fill<<<(EE+255)/256, 256>>>(ei);

    // fused geometry + radial + MLP1 (writes g_sh + CSR-ordered g_sh2)
    k_geomh<<<EE/128, 256, GEOMH_SMEM>>>(pos, rw1, rb1, ei);

    // GEMM2 -> g_wall (CSR order) + g_ew (edge order)
    dim3 gg(EE/128, 4);
    k_gemm<<<gg, 256, GEMM_SMEM>>>(rw2, edge_w, rb2, edge_b);

    // node features
    k_init<<<(NN*FD + 255)/256, 256>>>(node_embed, species);

    // 3 message-passing layers; last writes node rows of d_out directly
    for (int t = 0; t < 3; t++)
        k_layer<<<NN, 128>>>(t, self_w, msg_w, gate_w, out);

    // edge rows of d_out
    k_edge_out<<<EE/2, 256>>>(ei, out);
}